// round 1
// baseline (speedup 1.0000x reference)
#include <cuda_runtime.h>
#include <cuda_bf16.h>
#include <math.h>

// Problem constants (fixed instance)
#define NMAX   100000
#define EMAX   1600000
#define IN_DIM 256
#define HID    64      // HEADS*D1 = 8*8
#define HEADS  8
#define D1     8
#define NCLS   47
#define NEG_SLOPE 0.2f

// ---------------- device scratch (static allocation; no cudaMalloc) ----------------
__device__ int   g_is64;
__device__ int   g_src32[EMAX];
__device__ int   g_dst32[EMAX];
__device__ int   g_src_sorted[EMAX];
__device__ int   g_deg[NMAX];
__device__ int   g_rowptr[NMAX + 1];
__device__ int   g_cur[NMAX];

__device__ float g_fs1[(size_t)NMAX * HID];
__device__ float g_fd1[(size_t)NMAX * HID];
__device__ float g_h  [(size_t)NMAX * HID];
__device__ float g_fs2[(size_t)NMAX * NCLS];
__device__ float g_fd2[(size_t)NMAX * NCLS];
__device__ float g_es [(size_t)EMAX * HEADS];   // reused as [EMAX] in layer 2

__device__ float g_Wc1[IN_DIM * 2 * HID];       // [256][128] = [W1_src | W1_dst]
__device__ float g_bc1[2 * HID];
__device__ float g_Wc2[HID * 2 * NCLS];         // [64][94]  = [W2_src | W2_dst]
__device__ float g_bc2[2 * NCLS];

__device__ __forceinline__ float lrelu(float x) { return x > 0.f ? x : NEG_SLOPE * x; }
__device__ __forceinline__ float elu(float x)   { return x > 0.f ? x : expm1f(x); }

// ---------------- index dtype detection + conversion ----------------
__global__ void detect_kernel(const int* __restrict__ srcW) {
    // if indices are int64 (values < 1e5), every odd 32-bit word is 0.
    int ok64 = 1;
    #pragma unroll
    for (int i = 1; i < 16; i += 2) if (srcW[i] != 0) ok64 = 0;
    g_is64 = ok64;
}

__global__ void zero_deg_kernel(int N) {
    int v = blockIdx.x * blockDim.x + threadIdx.x;
    if (v < N) g_deg[v] = 0;
}

__global__ void convert_hist_kernel(const void* __restrict__ srcRaw,
                                    const void* __restrict__ dstRaw, int E) {
    int e = blockIdx.x * blockDim.x + threadIdx.x;
    if (e >= E) return;
    int s, d;
    if (g_is64) {
        s = (int)((const long long*)srcRaw)[e];
        d = (int)((const long long*)dstRaw)[e];
    } else {
        s = ((const int*)srcRaw)[e];
        d = ((const int*)dstRaw)[e];
    }
    g_src32[e] = s;
    g_dst32[e] = d;
    atomicAdd(&g_deg[d], 1);
}

// single-block exclusive scan over deg -> rowptr, cur
__global__ void scan_kernel(int N) {
    __shared__ int sums[1024];
    int t = threadIdx.x;
    int CH = (N + 1023) / 1024;
    int b = t * CH;
    int e = min(b + CH, N);
    int s = 0;
    for (int v = b; v < e; ++v) s += g_deg[v];
    sums[t] = s;
    __syncthreads();
    for (int off = 1; off < 1024; off <<= 1) {
        int val = (t >= off) ? sums[t - off] : 0;
        __syncthreads();
        sums[t] += val;
        __syncthreads();
    }
    int prefix = (t == 0) ? 0 : sums[t - 1];
    for (int v = b; v < e; ++v) {
        int d = g_deg[v];
        g_rowptr[v] = prefix;
        g_cur[v] = prefix;
        prefix += d;
    }
    if (t == 1023) g_rowptr[N] = sums[1023];
}

__global__ void scatter_kernel(int E) {
    int e = blockIdx.x * blockDim.x + threadIdx.x;
    if (e >= E) return;
    int d = g_dst32[e];
    int p = atomicAdd(&g_cur[d], 1);
    g_src_sorted[p] = g_src32[e];
}

// ---------------- weight packing ----------------
__global__ void combine1_kernel(const float* __restrict__ Ws, const float* __restrict__ bs,
                                const float* __restrict__ Wd, const float* __restrict__ bd) {
    int i = blockIdx.x * blockDim.x + threadIdx.x;
    int total = IN_DIM * 2 * HID;
    if (i < total) {
        int k = i / (2 * HID), c = i % (2 * HID);
        g_Wc1[i] = (c < HID) ? Ws[k * HID + c] : Wd[k * HID + (c - HID)];
    }
    if (i < 2 * HID) g_bc1[i] = (i < HID) ? bs[i] : bd[i - HID];
}

__global__ void combine2_kernel(const float* __restrict__ Ws, const float* __restrict__ bs,
                                const float* __restrict__ Wd, const float* __restrict__ bd) {
    int i = blockIdx.x * blockDim.x + threadIdx.x;
    int total = HID * 2 * NCLS;
    if (i < total) {
        int k = i / (2 * NCLS), c = i % (2 * NCLS);
        g_Wc2[i] = (c < NCLS) ? Ws[k * NCLS + c] : Wd[k * NCLS + (c - NCLS)];
    }
    if (i < 2 * NCLS) g_bc2[i] = (i < NCLS) ? bs[i] : bd[i - NCLS];
}

// ---------------- GEMM 1: x[M,256] @ Wc1[256,128] + bc1 -> fs1 | fd1 ----------------
__global__ void gemm1_kernel(const float* __restrict__ x, int M) {
    __shared__ float As[128][32];
    __shared__ float Bs[32][128];
    int tid = threadIdx.x;            // 256 threads
    int tx = tid & 15, ty = tid >> 4; // 16x16
    int row0 = blockIdx.x * 128;

    float acc[8][8];
    #pragma unroll
    for (int i = 0; i < 8; ++i)
        #pragma unroll
        for (int j = 0; j < 8; ++j) acc[i][j] = 0.f;

    for (int k0 = 0; k0 < IN_DIM; k0 += 32) {
        #pragma unroll
        for (int i = 0; i < 4; ++i) {
            int id = tid * 4 + i;
            int r = id >> 3, kq = id & 7;
            int grow = row0 + r;
            float4 v = (grow < M)
                ? ((const float4*)(x + (size_t)grow * IN_DIM + k0))[kq]
                : make_float4(0.f, 0.f, 0.f, 0.f);
            *(float4*)&As[r][kq * 4] = v;
        }
        #pragma unroll
        for (int i = 0; i < 4; ++i) {
            int id = tid * 4 + i;
            int r = id >> 5, cq = id & 31;
            *(float4*)&Bs[r][cq * 4] = *(const float4*)&g_Wc1[(k0 + r) * 128 + cq * 4];
        }
        __syncthreads();
        #pragma unroll
        for (int kk = 0; kk < 32; ++kk) {
            float a[8], b[8];
            #pragma unroll
            for (int i = 0; i < 8; ++i) a[i] = As[i * 16 + ty][kk];
            #pragma unroll
            for (int j = 0; j < 8; ++j) b[j] = Bs[kk][j * 16 + tx];
            #pragma unroll
            for (int i = 0; i < 8; ++i)
                #pragma unroll
                for (int j = 0; j < 8; ++j) acc[i][j] = fmaf(a[i], b[j], acc[i][j]);
        }
        __syncthreads();
    }
    #pragma unroll
    for (int i = 0; i < 8; ++i) {
        int grow = row0 + i * 16 + ty;
        if (grow >= M) continue;
        #pragma unroll
        for (int j = 0; j < 8; ++j) {
            int c = j * 16 + tx;
            float v = acc[i][j] + g_bc1[c];
            if (c < HID) g_fs1[(size_t)grow * HID + c] = v;
            else         g_fd1[(size_t)grow * HID + (c - HID)] = v;
        }
    }
}

// ---------------- GEMM 2: h[M,64] @ Wc2[64,94] + bc2 -> fs2 | fd2 ----------------
__global__ void gemm2_kernel(int M) {
    __shared__ float Hs[64][65];
    __shared__ float Ws[64][96];
    int tid = threadIdx.x;            // 256
    int tx = tid & 15, ty = tid >> 4;
    int row0 = blockIdx.x * 64;

    for (int idx = tid; idx < 64 * 2 * NCLS; idx += 256)
        Ws[idx / (2 * NCLS)][idx % (2 * NCLS)] = g_Wc2[idx];
    for (int idx = tid; idx < 64 * 64; idx += 256) {
        int r = idx >> 6, c = idx & 63;
        Hs[r][c] = (row0 + r < M) ? g_h[(size_t)(row0 + r) * HID + c] : 0.f;
    }
    __syncthreads();

    float acc[4][6];
    #pragma unroll
    for (int i = 0; i < 4; ++i)
        #pragma unroll
        for (int j = 0; j < 6; ++j) acc[i][j] = 0.f;

    #pragma unroll 8
    for (int k = 0; k < 64; ++k) {
        float a[4], b[6];
        #pragma unroll
        for (int i = 0; i < 4; ++i) a[i] = Hs[i * 16 + ty][k];
        #pragma unroll
        for (int j = 0; j < 6; ++j) b[j] = Ws[k][j * 16 + tx];
        #pragma unroll
        for (int i = 0; i < 4; ++i)
            #pragma unroll
            for (int j = 0; j < 6; ++j) acc[i][j] = fmaf(a[i], b[j], acc[i][j]);
    }
    #pragma unroll
    for (int i = 0; i < 4; ++i) {
        int grow = row0 + i * 16 + ty;
        if (grow >= M) continue;
        #pragma unroll
        for (int j = 0; j < 6; ++j) {
            int c = j * 16 + tx;
            if (c >= 2 * NCLS) continue;
            float v = acc[i][j] + g_bc2[c];
            if (c < NCLS) g_fs2[(size_t)grow * NCLS + c] = v;
            else          g_fd2[(size_t)grow * NCLS + (c - NCLS)] = v;
        }
    }
}

// ---------------- layer 1: warp per dst node (8 heads x 8 dims) ----------------
__global__ void layer1_kernel(int N, const float* __restrict__ attn1,
                              const float* __restrict__ bias1) {
    int w = (blockIdx.x * blockDim.x + threadIdx.x) >> 5;
    int lane = threadIdx.x & 31;
    if (w >= N) return;
    int start = g_rowptr[w], end = g_rowptr[w + 1];
    int i0 = lane, i1 = lane + 32;
    int h0 = lane >> 3, h1 = h0 + 4;

    float b0 = bias1[i0], b1 = bias1[i1];
    if (start == end) {
        g_h[(size_t)w * HID + i0] = elu(b0);
        g_h[(size_t)w * HID + i1] = elu(b1);
        return;
    }
    float fdv0 = g_fd1[(size_t)w * HID + i0];
    float fdv1 = g_fd1[(size_t)w * HID + i1];
    float att0 = attn1[i0], att1 = attn1[i1];

    // pass 1: scores e[p][h], per-head running max
    float mx0 = -INFINITY, mx1 = -INFINITY;
    for (int p = start; p < end; ++p) {
        int u = g_src_sorted[p];
        float t0 = lrelu(g_fs1[(size_t)u * HID + i0] + fdv0) * att0;
        float t1 = lrelu(g_fs1[(size_t)u * HID + i1] + fdv1) * att1;
        t0 += __shfl_xor_sync(0xffffffffu, t0, 1);
        t0 += __shfl_xor_sync(0xffffffffu, t0, 2);
        t0 += __shfl_xor_sync(0xffffffffu, t0, 4);
        t1 += __shfl_xor_sync(0xffffffffu, t1, 1);
        t1 += __shfl_xor_sync(0xffffffffu, t1, 2);
        t1 += __shfl_xor_sync(0xffffffffu, t1, 4);
        if ((lane & 7) == 0) {
            g_es[(size_t)p * HEADS + h0] = t0;
            g_es[(size_t)p * HEADS + h1] = t1;
        }
        mx0 = fmaxf(mx0, t0);
        mx1 = fmaxf(mx1, t1);
    }
    __syncwarp();
    __threadfence_block();

    // pass 2: ex = exp(e - m), per-head sum. lane handles head (lane&7), edge p+(lane>>3)
    int hh = lane & 7;
    float m_h = (hh < 4) ? __shfl_sync(0xffffffffu, mx0, hh << 3)
                         : __shfl_sync(0xffffffffu, mx1, (hh - 4) << 3);
    float s_lane = 0.f;
    for (int p = start; p < end; p += 4) {
        int idx = p + (lane >> 3);
        float ex = 0.f;
        if (idx < end) {
            float v = g_es[(size_t)idx * HEADS + hh];
            ex = __expf(v - m_h);
            g_es[(size_t)idx * HEADS + hh] = ex;
        }
        s_lane += ex;
    }
    s_lane += __shfl_xor_sync(0xffffffffu, s_lane, 8);
    s_lane += __shfl_xor_sync(0xffffffffu, s_lane, 16);
    __syncwarp();
    __threadfence_block();

    float s0 = __shfl_sync(0xffffffffu, s_lane, h0);
    float s1 = __shfl_sync(0xffffffffu, s_lane, h1);

    // pass 3: aggregate
    float acc0 = 0.f, acc1 = 0.f;
    for (int p = start; p < end; ++p) {
        int u = g_src_sorted[p];
        float ex0 = g_es[(size_t)p * HEADS + h0];
        float ex1 = g_es[(size_t)p * HEADS + h1];
        acc0 = fmaf(ex0, g_fs1[(size_t)u * HID + i0], acc0);
        acc1 = fmaf(ex1, g_fs1[(size_t)u * HID + i1], acc1);
    }
    float o0 = acc0 / s0 + b0;
    float o1 = acc1 / s1 + b1;
    g_h[(size_t)w * HID + i0] = elu(o0);
    g_h[(size_t)w * HID + i1] = elu(o1);
}

// ---------------- layer 2: warp per dst node (1 head x 47 dims) ----------------
__global__ void layer2_kernel(int N, const float* __restrict__ attn2,
                              const float* __restrict__ bias2,
                              float* __restrict__ out) {
    int w = (blockIdx.x * blockDim.x + threadIdx.x) >> 5;
    int lane = threadIdx.x & 31;
    if (w >= N) return;
    int start = g_rowptr[w], end = g_rowptr[w + 1];
    int c0 = lane, c1 = lane + 32;
    bool has1 = (c1 < NCLS);

    float b0 = bias2[c0];
    float b1 = has1 ? bias2[c1] : 0.f;
    if (start == end) {
        out[(size_t)w * NCLS + c0] = b0;
        if (has1) out[(size_t)w * NCLS + c1] = b1;
        return;
    }
    float fdv0 = g_fd2[(size_t)w * NCLS + c0];
    float fdv1 = has1 ? g_fd2[(size_t)w * NCLS + c1] : 0.f;
    float att0 = attn2[c0];
    float att1 = has1 ? attn2[c1] : 0.f;

    float mx = -INFINITY;
    for (int p = start; p < end; ++p) {
        int u = g_src_sorted[p];
        float t = lrelu(g_fs2[(size_t)u * NCLS + c0] + fdv0) * att0;
        if (has1) t += lrelu(g_fs2[(size_t)u * NCLS + c1] + fdv1) * att1;
        t += __shfl_xor_sync(0xffffffffu, t, 1);
        t += __shfl_xor_sync(0xffffffffu, t, 2);
        t += __shfl_xor_sync(0xffffffffu, t, 4);
        t += __shfl_xor_sync(0xffffffffu, t, 8);
        t += __shfl_xor_sync(0xffffffffu, t, 16);
        if (lane == 0) g_es[p] = t;
        mx = fmaxf(mx, t);
    }
    __syncwarp();
    __threadfence_block();

    float s = 0.f;
    for (int p = start; p < end; p += 32) {
        int idx = p + lane;
        float ex = 0.f;
        if (idx < end) {
            ex = __expf(g_es[idx] - mx);
            g_es[idx] = ex;
        }
        s += ex;
    }
    s += __shfl_xor_sync(0xffffffffu, s, 1);
    s += __shfl_xor_sync(0xffffffffu, s, 2);
    s += __shfl_xor_sync(0xffffffffu, s, 4);
    s += __shfl_xor_sync(0xffffffffu, s, 8);
    s += __shfl_xor_sync(0xffffffffu, s, 16);
    __syncwarp();
    __threadfence_block();

    float acc0 = 0.f, acc1 = 0.f;
    for (int p = start; p < end; ++p) {
        int u = g_src_sorted[p];
        float ex = g_es[p];
        acc0 = fmaf(ex, g_fs2[(size_t)u * NCLS + c0], acc0);
        if (has1) acc1 = fmaf(ex, g_fs2[(size_t)u * NCLS + c1], acc1);
    }
    out[(size_t)w * NCLS + c0] = acc0 / s + b0;
    if (has1) out[(size_t)w * NCLS + c1] = acc1 / s + b1;
}

// ---------------- launch ----------------
extern "C" void kernel_launch(void* const* d_in, const int* in_sizes, int n_in,
                              void* d_out, int out_size) {
    const float* x      = (const float*)d_in[0];
    const void*  srcRaw = d_in[1];
    const void*  dstRaw = d_in[2];
    const float* W1s = (const float*)d_in[3];
    const float* b1s = (const float*)d_in[4];
    const float* W1d = (const float*)d_in[5];
    const float* b1d = (const float*)d_in[6];
    const float* attn1 = (const float*)d_in[7];
    const float* bias1 = (const float*)d_in[8];
    const float* W2s = (const float*)d_in[9];
    const float* b2s = (const float*)d_in[10];
    const float* W2d = (const float*)d_in[11];
    const float* b2d = (const float*)d_in[12];
    const float* attn2 = (const float*)d_in[13];
    const float* bias2 = (const float*)d_in[14];
    float* out = (float*)d_out;

    int N = in_sizes[0] / IN_DIM;   // 100000
    int E = in_sizes[1];            // 1600000

    detect_kernel<<<1, 1>>>((const int*)srcRaw);
    zero_deg_kernel<<<(N + 255) / 256, 256>>>(N);
    convert_hist_kernel<<<(E + 255) / 256, 256>>>(srcRaw, dstRaw, E);
    scan_kernel<<<1, 1024>>>(N);
    scatter_kernel<<<(E + 255) / 256, 256>>>(E);

    combine1_kernel<<<(IN_DIM * 2 * HID + 255) / 256, 256>>>(W1s, b1s, W1d, b1d);
    combine2_kernel<<<(HID * 2 * NCLS + 255) / 256, 256>>>(W2s, b2s, W2d, b2d);

    gemm1_kernel<<<(N + 127) / 128, 256>>>(x, N);
    layer1_kernel<<<(N + 7) / 8, 256>>>(N, attn1, bias1);
    gemm2_kernel<<<(N + 63) / 64, 256>>>(N);
    layer2_kernel<<<(N + 7) / 8, 256>>>(N, attn2, bias2, out);
}

// round 4
// speedup vs baseline: 1.4593x; 1.4593x over previous
#include <cuda_runtime.h>
#include <cuda_bf16.h>
#include <math.h>

// Problem constants (fixed instance)
#define NMAX   100000
#define EMAX   1600000
#define IN_DIM 256
#define HID    64      // HEADS*D1 = 8*8
#define HEADS  8
#define D1     8
#define NCLS   47
#define NEG_SLOPE 0.2f

// ---------------- device scratch (static allocation; no cudaMalloc) ----------------
__device__ int   g_is64;
__device__ int   g_src32[EMAX];
__device__ int   g_dst32[EMAX];
__device__ int   g_src_sorted[EMAX];
__device__ int   g_deg[NMAX];
__device__ int   g_rowptr[NMAX + 1];
__device__ int   g_cur[NMAX];
__device__ int   g_bsum[128];           // >= ceil(NMAX/1024)=98 block sums

__device__ float g_fs1[(size_t)NMAX * HID];
__device__ float g_fd1[(size_t)NMAX * HID];
__device__ float g_h  [(size_t)NMAX * HID];
__device__ float g_fs2[(size_t)NMAX * NCLS];
__device__ float g_fd2[(size_t)NMAX * NCLS];

__device__ float g_Wc1[IN_DIM * 2 * HID];       // [256][128] = [W1_src | W1_dst]
__device__ float g_bc1[2 * HID];
__device__ float g_Wc2[HID * 2 * NCLS];         // [64][94]  = [W2_src | W2_dst]
__device__ float g_bc2[2 * NCLS];

__device__ __forceinline__ float lrelu(float x) { return x > 0.f ? x : NEG_SLOPE * x; }
__device__ __forceinline__ float elu(float x)   { return x > 0.f ? x : expm1f(x); }

// ---------------- index dtype detection + conversion ----------------
__global__ void detect_kernel(const int* __restrict__ srcW) {
    // if indices are int64 (values < 1e5), every odd 32-bit word is 0.
    int ok64 = 1;
    #pragma unroll
    for (int i = 1; i < 16; i += 2) if (srcW[i] != 0) ok64 = 0;
    g_is64 = ok64;
}

__global__ void zero_deg_kernel(int N) {
    int v = blockIdx.x * blockDim.x + threadIdx.x;
    if (v < N) g_deg[v] = 0;
}

__global__ void convert_hist_kernel(const void* __restrict__ srcRaw,
                                    const void* __restrict__ dstRaw, int E) {
    int e = blockIdx.x * blockDim.x + threadIdx.x;
    if (e >= E) return;
    int s, d;
    if (g_is64) {
        s = (int)((const long long*)srcRaw)[e];
        d = (int)((const long long*)dstRaw)[e];
    } else {
        s = ((const int*)srcRaw)[e];
        d = ((const int*)dstRaw)[e];
    }
    g_src32[e] = s;
    g_dst32[e] = d;
    atomicAdd(&g_deg[d], 1);
}

// ---------------- 3-phase multi-block exclusive scan of g_deg -> g_rowptr ----------------
__global__ void scan_phase1(int N) {
    __shared__ int sh[1024];
    int t = threadIdx.x;
    int i = blockIdx.x * 1024 + t;
    int v = (i < N) ? g_deg[i] : 0;
    sh[t] = v;
    __syncthreads();
    #pragma unroll
    for (int off = 1; off < 1024; off <<= 1) {
        int x = (t >= off) ? sh[t - off] : 0;
        __syncthreads();
        sh[t] += x;
        __syncthreads();
    }
    if (i < N) g_rowptr[i] = sh[t] - v;         // local exclusive
    if (t == 1023) g_bsum[blockIdx.x] = sh[1023];
}

__global__ void scan_phase2(int nb, int N) {
    __shared__ int sh[128];
    int t = threadIdx.x;
    int v = (t < nb) ? g_bsum[t] : 0;
    sh[t] = v;
    __syncthreads();
    #pragma unroll
    for (int off = 1; off < 128; off <<= 1) {
        int x = (t >= off) ? sh[t - off] : 0;
        __syncthreads();
        sh[t] += x;
        __syncthreads();
    }
    if (t < nb) g_bsum[t] = sh[t] - v;          // exclusive block offsets
    if (t == 127) g_rowptr[N] = sh[127];        // total = E
}

__global__ void scan_phase3(int N) {
    int i = blockIdx.x * blockDim.x + threadIdx.x;
    if (i < N) {
        int r = g_rowptr[i] + g_bsum[i >> 10];
        g_rowptr[i] = r;
        g_cur[i] = r;
    }
}

__global__ void scatter_kernel(int E) {
    int e = blockIdx.x * blockDim.x + threadIdx.x;
    if (e >= E) return;
    int d = g_dst32[e];
    int p = atomicAdd(&g_cur[d], 1);
    g_src_sorted[p] = g_src32[e];
}

// ---------------- weight packing ----------------
__global__ void combine1_kernel(const float* __restrict__ Ws, const float* __restrict__ bs,
                                const float* __restrict__ Wd, const float* __restrict__ bd) {
    int i = blockIdx.x * blockDim.x + threadIdx.x;
    int total = IN_DIM * 2 * HID;
    if (i < total) {
        int k = i / (2 * HID), c = i % (2 * HID);
        g_Wc1[i] = (c < HID) ? Ws[k * HID + c] : Wd[k * HID + (c - HID)];
    }
    if (i < 2 * HID) g_bc1[i] = (i < HID) ? bs[i] : bd[i - HID];
}

__global__ void combine2_kernel(const float* __restrict__ Ws, const float* __restrict__ bs,
                                const float* __restrict__ Wd, const float* __restrict__ bd) {
    int i = blockIdx.x * blockDim.x + threadIdx.x;
    int total = HID * 2 * NCLS;
    if (i < total) {
        int k = i / (2 * NCLS), c = i % (2 * NCLS);
        g_Wc2[i] = (c < NCLS) ? Ws[k * NCLS + c] : Wd[k * NCLS + (c - NCLS)];
    }
    if (i < 2 * NCLS) g_bc2[i] = (i < NCLS) ? bs[i] : bd[i - NCLS];
}

// ---------------- GEMM 1: x[M,256] @ Wc1[256,128] + bc1 -> fs1 | fd1 ----------------
__global__ void gemm1_kernel(const float* __restrict__ x, int M) {
    __shared__ float As[128][32];
    __shared__ float Bs[32][128];
    int tid = threadIdx.x;            // 256 threads
    int tx = tid & 15, ty = tid >> 4; // 16x16
    int row0 = blockIdx.x * 128;

    float acc[8][8];
    #pragma unroll
    for (int i = 0; i < 8; ++i)
        #pragma unroll
        for (int j = 0; j < 8; ++j) acc[i][j] = 0.f;

    for (int k0 = 0; k0 < IN_DIM; k0 += 32) {
        #pragma unroll
        for (int i = 0; i < 4; ++i) {
            int id = tid * 4 + i;
            int r = id >> 3, kq = id & 7;
            int grow = row0 + r;
            float4 v = (grow < M)
                ? ((const float4*)(x + (size_t)grow * IN_DIM + k0))[kq]
                : make_float4(0.f, 0.f, 0.f, 0.f);
            *(float4*)&As[r][kq * 4] = v;
        }
        #pragma unroll
        for (int i = 0; i < 4; ++i) {
            int id = tid * 4 + i;
            int r = id >> 5, cq = id & 31;
            *(float4*)&Bs[r][cq * 4] = *(const float4*)&g_Wc1[(k0 + r) * 128 + cq * 4];
        }
        __syncthreads();
        #pragma unroll
        for (int kk = 0; kk < 32; ++kk) {
            float a[8], b[8];
            #pragma unroll
            for (int i = 0; i < 8; ++i) a[i] = As[i * 16 + ty][kk];
            #pragma unroll
            for (int j = 0; j < 8; ++j) b[j] = Bs[kk][j * 16 + tx];
            #pragma unroll
            for (int i = 0; i < 8; ++i)
                #pragma unroll
                for (int j = 0; j < 8; ++j) acc[i][j] = fmaf(a[i], b[j], acc[i][j]);
        }
        __syncthreads();
    }
    #pragma unroll
    for (int i = 0; i < 8; ++i) {
        int grow = row0 + i * 16 + ty;
        if (grow >= M) continue;
        #pragma unroll
        for (int j = 0; j < 8; ++j) {
            int c = j * 16 + tx;
            float v = acc[i][j] + g_bc1[c];
            if (c < HID) g_fs1[(size_t)grow * HID + c] = v;
            else         g_fd1[(size_t)grow * HID + (c - HID)] = v;
        }
    }
}

// ---------------- GEMM 2: h[M,64] @ Wc2[64,94] + bc2 -> fs2 | fd2 ----------------
__global__ void gemm2_kernel(int M) {
    __shared__ float Hs[64][65];
    __shared__ float Ws[64][96];
    int tid = threadIdx.x;            // 256
    int tx = tid & 15, ty = tid >> 4;
    int row0 = blockIdx.x * 64;

    for (int idx = tid; idx < 64 * 2 * NCLS; idx += 256)
        Ws[idx / (2 * NCLS)][idx % (2 * NCLS)] = g_Wc2[idx];
    for (int idx = tid; idx < 64 * 64; idx += 256) {
        int r = idx >> 6, c = idx & 63;
        Hs[r][c] = (row0 + r < M) ? g_h[(size_t)(row0 + r) * HID + c] : 0.f;
    }
    __syncthreads();

    float acc[4][6];
    #pragma unroll
    for (int i = 0; i < 4; ++i)
        #pragma unroll
        for (int j = 0; j < 6; ++j) acc[i][j] = 0.f;

    #pragma unroll 8
    for (int k = 0; k < 64; ++k) {
        float a[4], b[6];
        #pragma unroll
        for (int i = 0; i < 4; ++i) a[i] = Hs[i * 16 + ty][k];
        #pragma unroll
        for (int j = 0; j < 6; ++j) b[j] = Ws[k][j * 16 + tx];
        #pragma unroll
        for (int i = 0; i < 4; ++i)
            #pragma unroll
            for (int j = 0; j < 6; ++j) acc[i][j] = fmaf(a[i], b[j], acc[i][j]);
    }
    #pragma unroll
    for (int i = 0; i < 4; ++i) {
        int grow = row0 + i * 16 + ty;
        if (grow >= M) continue;
        #pragma unroll
        for (int j = 0; j < 6; ++j) {
            int c = j * 16 + tx;
            if (c >= 2 * NCLS) continue;
            float v = acc[i][j] + g_bc2[c];
            if (c < NCLS) g_fs2[(size_t)grow * NCLS + c] = v;
            else          g_fd2[(size_t)grow * NCLS + (c - NCLS)] = v;
        }
    }
}

// ---------------- layer 1: warp per dst node, single-pass online softmax ----------------
__global__ void layer1_kernel(int N, const float* __restrict__ attn1,
                              const float* __restrict__ bias1) {
    int w = (blockIdx.x * blockDim.x + threadIdx.x) >> 5;
    int lane = threadIdx.x & 31;
    if (w >= N) return;
    int start = g_rowptr[w], end = g_rowptr[w + 1];
    int i0 = lane, i1 = lane + 32;

    float b0 = bias1[i0], b1 = bias1[i1];
    if (start == end) {
        g_h[(size_t)w * HID + i0] = elu(b0);
        g_h[(size_t)w * HID + i1] = elu(b1);
        return;
    }
    float fdv0 = g_fd1[(size_t)w * HID + i0];
    float fdv1 = g_fd1[(size_t)w * HID + i1];
    float att0 = attn1[i0], att1 = attn1[i1];

    // online softmax state per lane (uniform within each 8-lane head group)
    float mx0 = -INFINITY, mx1 = -INFINITY;
    float s0 = 0.f, s1 = 0.f;
    float acc0 = 0.f, acc1 = 0.f;

    for (int p = start; p < end; ++p) {
        int u = g_src_sorted[p];
        float f0 = g_fs1[(size_t)u * HID + i0];
        float f1 = g_fs1[(size_t)u * HID + i1];
        float t0 = lrelu(f0 + fdv0) * att0;
        float t1 = lrelu(f1 + fdv1) * att1;
        t0 += __shfl_xor_sync(0xffffffffu, t0, 1);
        t0 += __shfl_xor_sync(0xffffffffu, t0, 2);
        t0 += __shfl_xor_sync(0xffffffffu, t0, 4);
        t1 += __shfl_xor_sync(0xffffffffu, t1, 1);
        t1 += __shfl_xor_sync(0xffffffffu, t1, 2);
        t1 += __shfl_xor_sync(0xffffffffu, t1, 4);
        // one exp covers both rescale and weight: exp(-|t - m|)
        float ed0 = __expf(0.f - fabsf(t0 - mx0));
        float ed1 = __expf(0.f - fabsf(t1 - mx1));
        bool up0 = t0 > mx0;
        bool up1 = t1 > mx1;
        float sc0 = up0 ? ed0 : 1.f;
        float w0  = up0 ? 1.f : ed0;
        float sc1 = up1 ? ed1 : 1.f;
        float w1  = up1 ? 1.f : ed1;
        mx0 = fmaxf(mx0, t0);
        mx1 = fmaxf(mx1, t1);
        s0 = fmaf(s0, sc0, w0);
        s1 = fmaf(s1, sc1, w1);
        acc0 = fmaf(acc0, sc0, w0 * f0);
        acc1 = fmaf(acc1, sc1, w1 * f1);
    }
    float o0 = acc0 / s0 + b0;
    float o1 = acc1 / s1 + b1;
    g_h[(size_t)w * HID + i0] = elu(o0);
    g_h[(size_t)w * HID + i1] = elu(o1);
}

// ---------------- layer 2: warp per dst node, single-pass online softmax ----------------
__global__ void layer2_kernel(int N, const float* __restrict__ attn2,
                              const float* __restrict__ bias2,
                              float* __restrict__ out) {
    int w = (blockIdx.x * blockDim.x + threadIdx.x) >> 5;
    int lane = threadIdx.x & 31;
    if (w >= N) return;
    int start = g_rowptr[w], end = g_rowptr[w + 1];
    int c0 = lane, c1 = lane + 32;
    bool has1 = (c1 < NCLS);

    float b0 = bias2[c0];
    float b1 = has1 ? bias2[c1] : 0.f;
    if (start == end) {
        out[(size_t)w * NCLS + c0] = b0;
        if (has1) out[(size_t)w * NCLS + c1] = b1;
        return;
    }
    float fdv0 = g_fd2[(size_t)w * NCLS + c0];
    float fdv1 = has1 ? g_fd2[(size_t)w * NCLS + c1] : 0.f;
    float att0 = attn2[c0];
    float att1 = has1 ? attn2[c1] : 0.f;

    float mx = -INFINITY, s = 0.f;
    float acc0 = 0.f, acc1 = 0.f;

    for (int p = start; p < end; ++p) {
        int u = g_src_sorted[p];
        float f0 = g_fs2[(size_t)u * NCLS + c0];
        float f1 = has1 ? g_fs2[(size_t)u * NCLS + c1] : 0.f;
        float t = lrelu(f0 + fdv0) * att0;
        if (has1) t += lrelu(f1 + fdv1) * att1;
        t += __shfl_xor_sync(0xffffffffu, t, 1);
        t += __shfl_xor_sync(0xffffffffu, t, 2);
        t += __shfl_xor_sync(0xffffffffu, t, 4);
        t += __shfl_xor_sync(0xffffffffu, t, 8);
        t += __shfl_xor_sync(0xffffffffu, t, 16);
        float ed = __expf(0.f - fabsf(t - mx));
        bool up = t > mx;
        float sc = up ? ed : 1.f;
        float wt = up ? 1.f : ed;
        mx = fmaxf(mx, t);
        s = fmaf(s, sc, wt);
        acc0 = fmaf(acc0, sc, wt * f0);
        acc1 = fmaf(acc1, sc, wt * f1);
    }
    out[(size_t)w * NCLS + c0] = acc0 / s + b0;
    if (has1) out[(size_t)w * NCLS + c1] = acc1 / s + b1;
}

// ---------------- launch ----------------
extern "C" void kernel_launch(void* const* d_in, const int* in_sizes, int n_in,
                              void* d_out, int out_size) {
    const float* x      = (const float*)d_in[0];
    const void*  srcRaw = d_in[1];
    const void*  dstRaw = d_in[2];
    const float* W1s = (const float*)d_in[3];
    const float* b1s = (const float*)d_in[4];
    const float* W1d = (const float*)d_in[5];
    const float* b1d = (const float*)d_in[6];
    const float* attn1 = (const float*)d_in[7];
    const float* bias1 = (const float*)d_in[8];
    const float* W2s = (const float*)d_in[9];
    const float* b2s = (const float*)d_in[10];
    const float* W2d = (const float*)d_in[11];
    const float* b2d = (const float*)d_in[12];
    const float* attn2 = (const float*)d_in[13];
    const float* bias2 = (const float*)d_in[14];
    float* out = (float*)d_out;

    int N = in_sizes[0] / IN_DIM;   // 100000
    int E = in_sizes[1];            // 1600000
    int nb = (N + 1023) >> 10;      // scan blocks (98)

    detect_kernel<<<1, 1>>>((const int*)srcRaw);
    zero_deg_kernel<<<(N + 255) / 256, 256>>>(N);
    convert_hist_kernel<<<(E + 255) / 256, 256>>>(srcRaw, dstRaw, E);
    scan_phase1<<<nb, 1024>>>(N);
    scan_phase2<<<1, 128>>>(nb, N);
    scan_phase3<<<(N + 255) / 256, 256>>>(N);
    scatter_kernel<<<(E + 255) / 256, 256>>>(E);

    combine1_kernel<<<(IN_DIM * 2 * HID + 255) / 256, 256>>>(W1s, b1s, W1d, b1d);
    combine2_kernel<<<(HID * 2 * NCLS + 255) / 256, 256>>>(W2s, b2s, W2d, b2d);

    gemm1_kernel<<<(N + 127) / 128, 256>>>(x, N);
    layer1_kernel<<<(N + 7) / 8, 256>>>(N, attn1, bias1);
    gemm2_kernel<<<(N + 63) / 64, 256>>>(N);
    layer2_kernel<<<(N + 7) / 8, 256>>>(N, attn2, bias2, out);
}

// round 5
// speedup vs baseline: 2.1053x; 1.4427x over previous
#include <cuda_runtime.h>
#include <cuda_bf16.h>
#include <math.h>
#include <stdint.h>

// Problem constants (fixed instance)
#define NMAX   100000
#define EMAX   1600000
#define IN_DIM 256
#define HID    64      // HEADS*D1 = 8*8
#define HEADS  8
#define D1     8
#define NCLS   47
#define NC2P   48      // padded stride for layer-2 feature arrays
#define NEG_SLOPE 0.2f

// ---------------- device scratch (static allocation; no cudaMalloc) ----------------
__device__ int   g_is64;
__device__ int   g_src32[EMAX];
__device__ int   g_dst32[EMAX];
__device__ int   g_src_sorted[EMAX];
__device__ int   g_deg[NMAX];
__device__ int   g_rowptr[NMAX + 1];
__device__ int   g_cur[NMAX];
__device__ int   g_bsum[128];           // >= ceil(NMAX/1024)=98 block sums

__device__ float g_fs1[(size_t)NMAX * HID];
__device__ float g_fd1[(size_t)NMAX * HID];
__device__ float g_h  [(size_t)NMAX * HID];
__device__ float g_fs2[(size_t)NMAX * NC2P];
__device__ float g_fd2[(size_t)NMAX * NC2P];

__device__ float g_Wc1[IN_DIM * 2 * HID];       // [256][128] = [W1_src | W1_dst]
__device__ float g_bc1[2 * HID];
__device__ float g_Wc2[HID * 2 * NCLS];         // [64][94]  = [W2_src | W2_dst]
__device__ float g_bc2[2 * NCLS];

__device__ __forceinline__ float lrelu(float x) { return x > 0.f ? x : NEG_SLOPE * x; }
__device__ __forceinline__ float elu(float x)   { return x > 0.f ? x : expm1f(x); }

// ---------------- index dtype detection + conversion ----------------
__global__ void detect_kernel(const int* __restrict__ srcW) {
    int ok64 = 1;
    #pragma unroll
    for (int i = 1; i < 16; i += 2) if (srcW[i] != 0) ok64 = 0;
    g_is64 = ok64;
}

__global__ void zero_deg_kernel(int N) {
    int v = blockIdx.x * blockDim.x + threadIdx.x;
    if (v < N) g_deg[v] = 0;
}

__global__ void convert_hist_kernel(const void* __restrict__ srcRaw,
                                    const void* __restrict__ dstRaw, int E) {
    int e = blockIdx.x * blockDim.x + threadIdx.x;
    if (e >= E) return;
    int s, d;
    if (g_is64) {
        s = (int)((const long long*)srcRaw)[e];
        d = (int)((const long long*)dstRaw)[e];
    } else {
        s = ((const int*)srcRaw)[e];
        d = ((const int*)dstRaw)[e];
    }
    g_src32[e] = s;
    g_dst32[e] = d;
    atomicAdd(&g_deg[d], 1);
}

// ---------------- 3-phase multi-block exclusive scan of g_deg -> g_rowptr ----------------
__global__ void scan_phase1(int N) {
    __shared__ int sh[1024];
    int t = threadIdx.x;
    int i = blockIdx.x * 1024 + t;
    int v = (i < N) ? g_deg[i] : 0;
    sh[t] = v;
    __syncthreads();
    #pragma unroll
    for (int off = 1; off < 1024; off <<= 1) {
        int x = (t >= off) ? sh[t - off] : 0;
        __syncthreads();
        sh[t] += x;
        __syncthreads();
    }
    if (i < N) g_rowptr[i] = sh[t] - v;
    if (t == 1023) g_bsum[blockIdx.x] = sh[1023];
}

__global__ void scan_phase2(int nb, int N) {
    __shared__ int sh[128];
    int t = threadIdx.x;
    int v = (t < nb) ? g_bsum[t] : 0;
    sh[t] = v;
    __syncthreads();
    #pragma unroll
    for (int off = 1; off < 128; off <<= 1) {
        int x = (t >= off) ? sh[t - off] : 0;
        __syncthreads();
        sh[t] += x;
        __syncthreads();
    }
    if (t < nb) g_bsum[t] = sh[t] - v;
    if (t == 127) g_rowptr[N] = sh[127];
}

__global__ void scan_phase3(int N) {
    int i = blockIdx.x * blockDim.x + threadIdx.x;
    if (i < N) {
        int r = g_rowptr[i] + g_bsum[i >> 10];
        g_rowptr[i] = r;
        g_cur[i] = r;
    }
}

__global__ void scatter_kernel(int E) {
    int e = blockIdx.x * blockDim.x + threadIdx.x;
    if (e >= E) return;
    int d = g_dst32[e];
    int p = atomicAdd(&g_cur[d], 1);
    g_src_sorted[p] = g_src32[e];
}

// ---------------- weight packing ----------------
__global__ void combine1_kernel(const float* __restrict__ Ws, const float* __restrict__ bs,
                                const float* __restrict__ Wd, const float* __restrict__ bd) {
    int i = blockIdx.x * blockDim.x + threadIdx.x;
    int total = IN_DIM * 2 * HID;
    if (i < total) {
        int k = i / (2 * HID), c = i % (2 * HID);
        g_Wc1[i] = (c < HID) ? Ws[k * HID + c] : Wd[k * HID + (c - HID)];
    }
    if (i < 2 * HID) g_bc1[i] = (i < HID) ? bs[i] : bd[i - HID];
}

__global__ void combine2_kernel(const float* __restrict__ Ws, const float* __restrict__ bs,
                                const float* __restrict__ Wd, const float* __restrict__ bd) {
    int i = blockIdx.x * blockDim.x + threadIdx.x;
    int total = HID * 2 * NCLS;
    if (i < total) {
        int k = i / (2 * NCLS), c = i % (2 * NCLS);
        g_Wc2[i] = (c < NCLS) ? Ws[k * NCLS + c] : Wd[k * NCLS + (c - NCLS)];
    }
    if (i < 2 * NCLS) g_bc2[i] = (i < NCLS) ? bs[i] : bd[i - NCLS];
}

// ---------------- GEMM 1 (TF32 tensor cores): x[M,256] @ Wc1[256,128] -> fs1|fd1 ----------------
// 256 threads = 8 warps; block tile 128x128; warp tile 16x128; K-chunk 32, mma m16n8k8.
__global__ void gemm1_tc_kernel(const float* __restrict__ x, int M) {
    __shared__ float As[128][36];    // pad 36: conflict-free frag reads, 16B-aligned stores
    __shared__ float Bs[32][136];    // pad 136: conflict-free frag reads
    int tid  = threadIdx.x;
    int lane = tid & 31;
    int warp = tid >> 5;             // 0..7
    int row0 = blockIdx.x * 128;
    int warpRow = warp * 16;
    int gid = lane >> 2;             // groupID 0..7
    int tig = lane & 3;              // thread-in-group 0..3

    float c[16][4];
    #pragma unroll
    for (int j = 0; j < 16; ++j)
        #pragma unroll
        for (int q = 0; q < 4; ++q) c[j][q] = 0.f;

    for (int k0 = 0; k0 < IN_DIM; k0 += 32) {
        // load A tile 128x32 (float4)
        #pragma unroll
        for (int i = 0; i < 4; ++i) {
            int id = tid * 4 + i;            // 0..1023
            int r = id >> 3, q = id & 7;
            int grow = row0 + r;
            float4 v = (grow < M)
                ? *(const float4*)(x + (size_t)grow * IN_DIM + k0 + q * 4)
                : make_float4(0.f, 0.f, 0.f, 0.f);
            *(float4*)&As[r][q * 4] = v;
        }
        // load B tile 32x128 (float4)
        #pragma unroll
        for (int i = 0; i < 4; ++i) {
            int id = tid * 4 + i;
            int r = id >> 5, q = id & 31;
            *(float4*)&Bs[r][q * 4] = *(const float4*)&g_Wc1[(k0 + r) * 128 + q * 4];
        }
        __syncthreads();
        #pragma unroll
        for (int kk = 0; kk < 32; kk += 8) {
            uint32_t a[4];
            {
                float a0 = As[warpRow + gid    ][kk + tig    ];
                float a1 = As[warpRow + gid + 8][kk + tig    ];
                float a2 = As[warpRow + gid    ][kk + tig + 4];
                float a3 = As[warpRow + gid + 8][kk + tig + 4];
                asm("cvt.rna.tf32.f32 %0, %1;" : "=r"(a[0]) : "f"(a0));
                asm("cvt.rna.tf32.f32 %0, %1;" : "=r"(a[1]) : "f"(a1));
                asm("cvt.rna.tf32.f32 %0, %1;" : "=r"(a[2]) : "f"(a2));
                asm("cvt.rna.tf32.f32 %0, %1;" : "=r"(a[3]) : "f"(a3));
            }
            #pragma unroll
            for (int j = 0; j < 16; ++j) {
                uint32_t b[2];
                float b0 = Bs[kk + tig    ][j * 8 + gid];
                float b1 = Bs[kk + tig + 4][j * 8 + gid];
                asm("cvt.rna.tf32.f32 %0, %1;" : "=r"(b[0]) : "f"(b0));
                asm("cvt.rna.tf32.f32 %0, %1;" : "=r"(b[1]) : "f"(b1));
                asm("mma.sync.aligned.m16n8k8.row.col.f32.tf32.tf32.f32 "
                    "{%0,%1,%2,%3}, {%4,%5,%6,%7}, {%8,%9}, {%0,%1,%2,%3};"
                    : "+f"(c[j][0]), "+f"(c[j][1]), "+f"(c[j][2]), "+f"(c[j][3])
                    : "r"(a[0]), "r"(a[1]), "r"(a[2]), "r"(a[3]),
                      "r"(b[0]), "r"(b[1]));
            }
        }
        __syncthreads();
    }
    // epilogue: c0,c1 -> (row gid, cols cb,cb+1); c2,c3 -> (row gid+8)
    int r0 = row0 + warpRow + gid;
    int r1 = r0 + 8;
    #pragma unroll
    for (int j = 0; j < 16; ++j) {
        int cb = j * 8 + tig * 2;
        float2 bv = *(const float2*)&g_bc1[cb];
        if (r0 < M) {
            float2 v = make_float2(c[j][0] + bv.x, c[j][1] + bv.y);
            if (cb < HID) *(float2*)&g_fs1[(size_t)r0 * HID + cb] = v;
            else          *(float2*)&g_fd1[(size_t)r0 * HID + cb - HID] = v;
        }
        if (r1 < M) {
            float2 v = make_float2(c[j][2] + bv.x, c[j][3] + bv.y);
            if (cb < HID) *(float2*)&g_fs1[(size_t)r1 * HID + cb] = v;
            else          *(float2*)&g_fd1[(size_t)r1 * HID + cb - HID] = v;
        }
    }
}

// ---------------- GEMM 2: h[M,64] @ Wc2[64,94] + bc2 -> fs2|fd2 (stride 48) ----------------
__global__ void gemm2_kernel(int M) {
    __shared__ float Hs[64][65];
    __shared__ float Ws[64][96];
    int tid = threadIdx.x;            // 256
    int tx = tid & 15, ty = tid >> 4;
    int row0 = blockIdx.x * 64;

    for (int idx = tid; idx < 64 * 2 * NCLS; idx += 256)
        Ws[idx / (2 * NCLS)][idx % (2 * NCLS)] = g_Wc2[idx];
    for (int idx = tid; idx < 64 * 64; idx += 256) {
        int r = idx >> 6, c = idx & 63;
        Hs[r][c] = (row0 + r < M) ? g_h[(size_t)(row0 + r) * HID + c] : 0.f;
    }
    __syncthreads();

    float acc[4][6];
    #pragma unroll
    for (int i = 0; i < 4; ++i)
        #pragma unroll
        for (int j = 0; j < 6; ++j) acc[i][j] = 0.f;

    #pragma unroll 8
    for (int k = 0; k < 64; ++k) {
        float a[4], b[6];
        #pragma unroll
        for (int i = 0; i < 4; ++i) a[i] = Hs[i * 16 + ty][k];
        #pragma unroll
        for (int j = 0; j < 6; ++j) b[j] = Ws[k][j * 16 + tx];
        #pragma unroll
        for (int i = 0; i < 4; ++i)
            #pragma unroll
            for (int j = 0; j < 6; ++j) acc[i][j] = fmaf(a[i], b[j], acc[i][j]);
    }
    #pragma unroll
    for (int i = 0; i < 4; ++i) {
        int grow = row0 + i * 16 + ty;
        if (grow >= M) continue;
        #pragma unroll
        for (int j = 0; j < 6; ++j) {
            int c = j * 16 + tx;
            if (c >= 2 * NCLS) continue;
            float v = acc[i][j] + g_bc2[c];
            if (c < NCLS) g_fs2[(size_t)grow * NC2P + c] = v;
            else          g_fd2[(size_t)grow * NC2P + (c - NCLS)] = v;
        }
    }
}

// ---------------- layer 1: warp/node, 2 dims per lane, head = 4-lane group ----------------
__global__ void layer1_kernel(int N, const float* __restrict__ attn1,
                              const float* __restrict__ bias1) {
    int w = (blockIdx.x * blockDim.x + threadIdx.x) >> 5;
    int lane = threadIdx.x & 31;
    if (w >= N) return;
    int start = g_rowptr[w], end = g_rowptr[w + 1];
    int j0 = 2 * lane;                               // dims j0, j0+1 (head = lane>>2)

    float2 bv = *(const float2*)&bias1[j0];
    if (start == end) {
        float2 o = make_float2(elu(bv.x), elu(bv.y));
        *(float2*)&g_h[(size_t)w * HID + j0] = o;
        return;
    }
    float2 fdv = *(const float2*)&g_fd1[(size_t)w * HID + j0];
    float2 att = *(const float2*)&attn1[j0];

    float mx = -INFINITY, s = 0.f;
    float accx = 0.f, accy = 0.f;

    for (int p = start; p < end; ++p) {
        int u = g_src_sorted[p];
        float2 f = *(const float2*)&g_fs1[(size_t)u * HID + j0];
        float t = lrelu(f.x + fdv.x) * att.x + lrelu(f.y + fdv.y) * att.y;
        t += __shfl_xor_sync(0xffffffffu, t, 1);
        t += __shfl_xor_sync(0xffffffffu, t, 2);     // head score, uniform in 4-lane group
        float ed = __expf(0.f - fabsf(t - mx));
        bool up = t > mx;
        float sc = up ? ed : 1.f;
        float wt = up ? 1.f : ed;
        mx = fmaxf(mx, t);
        s = fmaf(s, sc, wt);
        accx = fmaf(accx, sc, wt * f.x);
        accy = fmaf(accy, sc, wt * f.y);
    }
    float inv = 1.f / s;
    float2 o = make_float2(elu(accx * inv + bv.x), elu(accy * inv + bv.y));
    *(float2*)&g_h[(size_t)w * HID + j0] = o;
}

// ---------------- layer 2: warp/node, 2 classes per lane (padded stride 48) ----------------
__global__ void layer2_kernel(int N, const float* __restrict__ attn2,
                              const float* __restrict__ bias2,
                              float* __restrict__ out) {
    int w = (blockIdx.x * blockDim.x + threadIdx.x) >> 5;
    int lane = threadIdx.x & 31;
    if (w >= N) return;
    int start = g_rowptr[w], end = g_rowptr[w + 1];
    int j0 = 2 * lane;
    int off = j0 < 46 ? j0 : 46;                     // clamped, even -> aligned float2
    bool m0 = (j0 < NCLS), m1 = (j0 + 1 < NCLS);

    float b0 = m0 ? bias2[j0] : 0.f;
    float b1 = m1 ? bias2[j0 + 1] : 0.f;
    if (start == end) {
        if (m0) out[(size_t)w * NCLS + j0] = b0;
        if (m1) out[(size_t)w * NCLS + j0 + 1] = b1;
        return;
    }
    float2 fdr = *(const float2*)&g_fd2[(size_t)w * NC2P + off];
    float fdv0 = m0 ? fdr.x : 0.f;
    float fdv1 = m1 ? fdr.y : 0.f;
    float att0 = m0 ? attn2[j0] : 0.f;
    float att1 = m1 ? attn2[j0 + 1] : 0.f;

    float mx = -INFINITY, s = 0.f;
    float acc0 = 0.f, acc1 = 0.f;

    for (int p = start; p < end; ++p) {
        int u = g_src_sorted[p];
        float2 fr = *(const float2*)&g_fs2[(size_t)u * NC2P + off];
        float f0 = m0 ? fr.x : 0.f;
        float f1 = m1 ? fr.y : 0.f;
        float t = lrelu(f0 + fdv0) * att0 + lrelu(f1 + fdv1) * att1;
        t += __shfl_xor_sync(0xffffffffu, t, 1);
        t += __shfl_xor_sync(0xffffffffu, t, 2);
        t += __shfl_xor_sync(0xffffffffu, t, 4);
        t += __shfl_xor_sync(0xffffffffu, t, 8);
        t += __shfl_xor_sync(0xffffffffu, t, 16);
        float ed = __expf(0.f - fabsf(t - mx));
        bool up = t > mx;
        float sc = up ? ed : 1.f;
        float wt = up ? 1.f : ed;
        mx = fmaxf(mx, t);
        s = fmaf(s, sc, wt);
        acc0 = fmaf(acc0, sc, wt * f0);
        acc1 = fmaf(acc1, sc, wt * f1);
    }
    float inv = 1.f / s;
    if (m0) out[(size_t)w * NCLS + j0]     = acc0 * inv + b0;
    if (m1) out[(size_t)w * NCLS + j0 + 1] = acc1 * inv + b1;
}

// ---------------- launch ----------------
extern "C" void kernel_launch(void* const* d_in, const int* in_sizes, int n_in,
                              void* d_out, int out_size) {
    const float* x      = (const float*)d_in[0];
    const void*  srcRaw = d_in[1];
    const void*  dstRaw = d_in[2];
    const float* W1s = (const float*)d_in[3];
    const float* b1s = (const float*)d_in[4];
    const float* W1d = (const float*)d_in[5];
    const float* b1d = (const float*)d_in[6];
    const float* attn1 = (const float*)d_in[7];
    const float* bias1 = (const float*)d_in[8];
    const float* W2s = (const float*)d_in[9];
    const float* b2s = (const float*)d_in[10];
    const float* W2d = (const float*)d_in[11];
    const float* b2d = (const float*)d_in[12];
    const float* attn2 = (const float*)d_in[13];
    const float* bias2 = (const float*)d_in[14];
    float* out = (float*)d_out;

    int N = in_sizes[0] / IN_DIM;   // 100000
    int E = in_sizes[1];            // 1600000
    int nb = (N + 1023) >> 10;      // scan blocks (98)

    detect_kernel<<<1, 1>>>((const int*)srcRaw);
    zero_deg_kernel<<<(N + 255) / 256, 256>>>(N);
    convert_hist_kernel<<<(E + 255) / 256, 256>>>(srcRaw, dstRaw, E);
    scan_phase1<<<nb, 1024>>>(N);
    scan_phase2<<<1, 128>>>(nb, N);
    scan_phase3<<<(N + 255) / 256, 256>>>(N);
    scatter_kernel<<<(E + 255) / 256, 256>>>(E);

    combine1_kernel<<<(IN_DIM * 2 * HID + 255) / 256, 256>>>(W1s, b1s, W1d, b1d);
    combine2_kernel<<<(HID * 2 * NCLS + 255) / 256, 256>>>(W2s, b2s, W2d, b2d);

    gemm1_tc_kernel<<<(N + 127) / 128, 256>>>(x, N);
    layer1_kernel<<<(N + 7) / 8, 256>>>(N, attn1, bias1);
    gemm2_kernel<<<(N + 63) / 64, 256>>>(N);
    layer2_kernel<<<(N + 7) / 8, 256>>>(N, attn2, bias2, out);
}